// round 7
// baseline (speedup 1.0000x reference)
#include <cuda_runtime.h>
#include <cstdint>

// Problem constants: B=2, T=2048, C=1024, H=16, D=64
#define BB   2
#define TT   2048
#define CC   1024
#define NH   16
#define HD   64
#define MROWS (BB*TT)          // 4096

// Scratch buffers (no cudaMalloc allowed)
__device__ float g_qkv[(size_t)MROWS * 3 * CC];   // [B*T, 3C], tf32-rounded by GEMM1
__device__ float g_att[(size_t)MROWS * CC];       // [B*T, C], tf32-rounded
__device__ float g_xc[(size_t)MROWS * CC];        // x, tf32-rounded
__device__ float g_wqkv[(size_t)CC * 3 * CC];     // w_qkv, tf32-rounded (same layout)
__device__ float g_wout[(size_t)CC * CC];         // w_out, tf32-rounded

// ---------------------------------------------------------------------------
// helpers
// ---------------------------------------------------------------------------
__device__ __forceinline__ unsigned f2tf32u(float x) {
    unsigned r; asm("cvt.rna.tf32.f32 %0, %1;" : "=r"(r) : "f"(x)); return r;
}
__device__ __forceinline__ float f2tf32f(float x) {
    return __uint_as_float(f2tf32u(x));
}
__device__ __forceinline__ unsigned fasu(float x) { return __float_as_uint(x); }

__device__ __forceinline__ float fexp2(float x) {
    float r; asm("ex2.approx.f32 %0, %1;" : "=f"(r) : "f"(x)); return r;
}

__device__ __forceinline__ uint32_t smem_u32(const void* p) {
    uint32_t a;
    asm("{ .reg .u64 t; cvta.to.shared.u64 t, %1; cvt.u32.u64 %0, t; }" : "=r"(a) : "l"(p));
    return a;
}

__device__ __forceinline__ void cpa16(uint32_t dst, const void* src) {
    asm volatile("cp.async.cg.shared.global [%0], [%1], 16;" :: "r"(dst), "l"(src));
}
#define CPA_COMMIT()  asm volatile("cp.async.commit_group;" ::: "memory")
#define CPA_WAIT(n)   asm volatile("cp.async.wait_group %0;" :: "n"(n) : "memory")

// D += A(16x8) @ B(8x8), tf32 operands, fp32 accum
__device__ __forceinline__ void mma8(float4& d,
    unsigned a0, unsigned a1, unsigned a2, unsigned a3,
    unsigned b0, unsigned b1)
{
    asm volatile(
        "mma.sync.aligned.m16n8k8.row.col.f32.tf32.tf32.f32 "
        "{%0,%1,%2,%3}, {%4,%5,%6,%7}, {%8,%9}, {%0,%1,%2,%3};\n"
        : "+f"(d.x), "+f"(d.y), "+f"(d.z), "+f"(d.w)
        : "r"(a0), "r"(a1), "r"(a2), "r"(a3), "r"(b0), "r"(b1));
}

// ---------------------------------------------------------------------------
// prepass: tf32-round a buffer
// ---------------------------------------------------------------------------
__global__ void cvt_copy(const float* __restrict__ in, float* __restrict__ out, int n4)
{
    int i = blockIdx.x * blockDim.x + threadIdx.x;
    if (i < n4) {
        float4 v = ((const float4*)in)[i];
        ((float4*)out)[i] = make_float4(f2tf32f(v.x), f2tf32f(v.y),
                                        f2tf32f(v.z), f2tf32f(v.w));
    }
}

// ---------------------------------------------------------------------------
// tf32 GEMM via mma.sync, cp.async 3-stage pipeline.
// C[M,N] = A[M,K] @ B[K,N] + bias[N]; A,B pre-rounded to tf32.
// 128x128 CTA tile, BK=16, 256 threads (8 warps, 2m x 4n), warp tile 64x32.
// smem stage: A[128][20] (2560 f) + B[16][136] (2176 f) = 4736 floats.
// Conflict-free fragment loads: A bank=(20qr+qp), B bank=(8qp+qr).
// ROUND: tf32-round the output (for qkv feeding attention).
// ---------------------------------------------------------------------------
template<bool ROUND>
__global__ __launch_bounds__(256) void gemm_cpa(
    const float* __restrict__ A, const float* __restrict__ B,
    const float* __restrict__ bias, float* __restrict__ C,
    int M, int N, int K)
{
    extern __shared__ float sm[];
    const int SA = 2560;          // floats per A stage
    const int STG = 4736;         // floats per stage
    const uint32_t sbase = smem_u32(sm);

    const int tid  = threadIdx.x;
    const int lane = tid & 31, warp = tid >> 5;
    const int wm = warp & 1;      // 64-row half
    const int wn = warp >> 1;     // 32-col quarter
    const int qp = lane & 3, qr = lane >> 2;
    const int brow = blockIdx.y * 128;
    const int bcol = blockIdx.x * 128;

    float4 acc[4][4];
    #pragma unroll
    for (int i = 0; i < 4; ++i)
        #pragma unroll
        for (int j = 0; j < 4; ++j) acc[i][j] = make_float4(0.f, 0.f, 0.f, 0.f);

    const int NCH = K >> 4;

    // per-thread load roles (fixed)
    const int ar = tid >> 2, au = tid & 3;        // A: rows tid>>2 (+64), 16B unit
    const int bk = tid >> 5, bc = tid & 31;       // B: k rows tid>>5 (+8), 16B col unit
    const float* Ag = A + (size_t)(brow + ar) * K + au * 4;
    const float* Bg = B + (size_t)bk * N + bcol + bc * 4;

    auto load_stage = [&](int kt) {
        const int s = kt % 3;
        uint32_t as = sbase + (s * STG) * 4;
        uint32_t bs = as + SA * 4;
        cpa16(as + (ar * 20 + au * 4) * 4,          Ag + (size_t)kt * 16);
        cpa16(as + ((ar + 64) * 20 + au * 4) * 4,   Ag + (size_t)64 * K + (size_t)kt * 16);
        cpa16(bs + (bk * 136 + bc * 4) * 4,         Bg + (size_t)kt * 16 * N);
        cpa16(bs + ((bk + 8) * 136 + bc * 4) * 4,   Bg + (size_t)(kt * 16 + 8) * N);
        CPA_COMMIT();
    };

    load_stage(0);
    load_stage(1);

    for (int kt = 0; kt < NCH; ++kt) {
        if (kt + 2 < NCH) load_stage(kt + 2);
        if (kt + 2 < NCH)      { CPA_WAIT(2); }
        else if (kt + 1 < NCH) { CPA_WAIT(1); }
        else                   { CPA_WAIT(0); }
        __syncthreads();

        const float* As = sm + (kt % 3) * STG;
        const float* Bs = As + SA;
        #pragma unroll
        for (int ks = 0; ks < 2; ++ks) {
            const int k0 = ks * 8 + qp;
            unsigned af[4][4];
            #pragma unroll
            for (int mt = 0; mt < 4; ++mt) {
                int r = wm * 64 + mt * 16 + qr;
                af[mt][0] = fasu(As[r * 20 + k0]);
                af[mt][1] = fasu(As[(r + 8) * 20 + k0]);
                af[mt][2] = fasu(As[r * 20 + k0 + 4]);
                af[mt][3] = fasu(As[(r + 8) * 20 + k0 + 4]);
            }
            unsigned bf[4][2];
            #pragma unroll
            for (int nt = 0; nt < 4; ++nt) {
                int c = wn * 32 + nt * 8 + qr;
                bf[nt][0] = fasu(Bs[k0 * 136 + c]);
                bf[nt][1] = fasu(Bs[(k0 + 4) * 136 + c]);
            }
            #pragma unroll
            for (int mt = 0; mt < 4; ++mt)
                #pragma unroll
                for (int nt = 0; nt < 4; ++nt)
                    mma8(acc[mt][nt], af[mt][0], af[mt][1], af[mt][2], af[mt][3],
                         bf[nt][0], bf[nt][1]);
        }
        __syncthreads();
    }

    // ---- epilogue ----
    #pragma unroll
    for (int mt = 0; mt < 4; ++mt) {
        int r0 = brow + wm * 64 + mt * 16 + qr;
        #pragma unroll
        for (int nt = 0; nt < 4; ++nt) {
            int c = bcol + wn * 32 + nt * 8 + 2 * qp;
            float bx = bias[c], by = bias[c + 1];
            float2 v0 = make_float2(acc[mt][nt].x + bx, acc[mt][nt].y + by);
            float2 v1 = make_float2(acc[mt][nt].z + bx, acc[mt][nt].w + by);
            if (ROUND) {
                v0.x = f2tf32f(v0.x); v0.y = f2tf32f(v0.y);
                v1.x = f2tf32f(v1.x); v1.y = f2tf32f(v1.y);
            }
            *(float2*)(C + (size_t)r0       * N + c) = v0;
            *(float2*)(C + (size_t)(r0 + 8) * N + c) = v1;
        }
    }
}

// ---------------------------------------------------------------------------
// Flash attention, tf32 mma.sync, log2-domain softmax.
// CTA: 128 q-rows, 128 threads (4 warps x 2 subtiles of 16 rows).
// K/V tiles (64 keys) cp.async double-buffered; qkv pre-rounded to tf32.
// smem: Ks/Vs [2 buffers][64][68] = 69632 B dynamic.
// ---------------------------------------------------------------------------
__global__ __launch_bounds__(128) void attn_tf32(
    const float* __restrict__ qkv, float* __restrict__ out)
{
    extern __shared__ float sm[];
    const int KVS = 64 * 68;                 // floats per K (or V) tile
    const uint32_t sbase = smem_u32(sm);

    const int tid  = threadIdx.x;
    const int lane = tid & 31, w = tid >> 5;
    const int h = blockIdx.y, b = blockIdx.z;
    const int q0 = blockIdx.x * 128;
    const int qp = lane & 3;
    const int qr = lane >> 2;
    const unsigned FULL = 0xffffffffu;
    const float qscale = 0.125f * 1.44269504088896f;   // 1/sqrt(64) * log2(e)

    // ---- Q fragments: 2 subtiles of 16 rows each (log2-scaled, tf32) ----
    unsigned qa[2][8][4];
    #pragma unroll
    for (int t = 0; t < 2; ++t) {
        const float* Qg = qkv + (size_t)(b*TT + q0 + w*32 + t*16) * (3*CC) + h*HD;
        #pragma unroll
        for (int ks = 0; ks < 8; ++ks) {
            int c0 = ks * 8 + qp;
            qa[t][ks][0] = f2tf32u(Qg[(size_t)qr     * (3*CC) + c0    ] * qscale);
            qa[t][ks][1] = f2tf32u(Qg[(size_t)(qr+8) * (3*CC) + c0    ] * qscale);
            qa[t][ks][2] = f2tf32u(Qg[(size_t)qr     * (3*CC) + c0 + 4] * qscale);
            qa[t][ks][3] = f2tf32u(Qg[(size_t)(qr+8) * (3*CC) + c0 + 4] * qscale);
        }
    }

    float4 o[2][8];
    #pragma unroll
    for (int t = 0; t < 2; ++t)
        #pragma unroll
        for (int i = 0; i < 8; ++i) o[t][i] = make_float4(0.f, 0.f, 0.f, 0.f);
    float m0[2] = {-1e30f, -1e30f}, m1[2] = {-1e30f, -1e30f};
    float l0[2] = {0.f, 0.f},       l1[2] = {0.f, 0.f};

    const int rm6[2] = { (q0 + w*32) >> 6, (q0 + w*32 + 16) >> 6 };
    const int nd = (q0 + 127) >> 6;          // last key-tile index

    // K/V tile: 64 keys x 64 dims = 1024 16B-chunks each; 128 threads x 8 iters.
    auto loadkv = [&](int kt, int buf) {
        const float* kb = qkv + (size_t)(b*TT + kt*64) * (3*CC) + CC + h*HD;
        const float* vb = kb + CC;
        uint32_t ksm = sbase + (buf * 2 * KVS) * 4;
        uint32_t vsm = ksm + KVS * 4;
        #pragma unroll
        for (int i = 0; i < 8; ++i) {
            int idx = i * 128 + tid;          // 0..1023
            int key = idx >> 4;               // 0..63
            int d4  = (idx & 15) * 4;         // 0..60
            uint32_t off = (key * 68 + d4) * 4;
            const size_t g = (size_t)key * (3*CC) + d4;
            cpa16(ksm + off, kb + g);
            cpa16(vsm + off, vb + g);
        }
        CPA_COMMIT();
    };

    loadkv(0, 0);
    for (int kt = 0; kt <= nd; ++kt) {
        if (kt < nd) { loadkv(kt + 1, (kt + 1) & 1); CPA_WAIT(1); }
        else         { CPA_WAIT(0); }
        __syncthreads();
        const float* Ks = sm + (kt & 1) * 2 * KVS;
        const float* Vs = Ks + KVS;

        #pragma unroll
        for (int t = 0; t < 2; ++t) {
            if (kt > rm6[t]) continue;        // fully masked subtile

            // ---- S = Q @ K^T (16 x 64), log2 domain ----
            float4 s[8];
            #pragma unroll
            for (int nt = 0; nt < 8; ++nt) s[nt] = make_float4(0.f, 0.f, 0.f, 0.f);
            #pragma unroll
            for (int nt = 0; nt < 8; ++nt) {
                const int key = nt * 8 + qr;
                #pragma unroll
                for (int ks = 0; ks < 8; ++ks) {
                    const int d = ks * 8 + qp;
                    mma8(s[nt], qa[t][ks][0], qa[t][ks][1], qa[t][ks][2], qa[t][ks][3],
                         fasu(Ks[key * 68 + d]), fasu(Ks[key * 68 + d + 4]));
                }
            }

            // ---- causal mask (diagonal tile only) ----
            if (kt == rm6[t]) {
                const int rg0 = q0 + w*32 + t*16 + qr;
                const int rg1 = rg0 + 8;
                #pragma unroll
                for (int nt = 0; nt < 8; ++nt) {
                    int cg = kt * 64 + nt * 8 + 2 * qp;
                    if (cg     > rg0) s[nt].x = -1e30f;
                    if (cg + 1 > rg0) s[nt].y = -1e30f;
                    if (cg     > rg1) s[nt].z = -1e30f;
                    if (cg + 1 > rg1) s[nt].w = -1e30f;
                }
            }

            // ---- online softmax (base-2) ----
            float mx0 = -1e30f, mx1 = -1e30f;
            #pragma unroll
            for (int nt = 0; nt < 8; ++nt) {
                mx0 = fmaxf(mx0, fmaxf(s[nt].x, s[nt].y));
                mx1 = fmaxf(mx1, fmaxf(s[nt].z, s[nt].w));
            }
            mx0 = fmaxf(mx0, __shfl_xor_sync(FULL, mx0, 1));
            mx0 = fmaxf(mx0, __shfl_xor_sync(FULL, mx0, 2));
            mx1 = fmaxf(mx1, __shfl_xor_sync(FULL, mx1, 1));
            mx1 = fmaxf(mx1, __shfl_xor_sync(FULL, mx1, 2));

            float nm0 = fmaxf(m0[t], mx0), nm1 = fmaxf(m1[t], mx1);
            float al0 = fexp2(m0[t] - nm0), al1 = fexp2(m1[t] - nm1);
            m0[t] = nm0; m1[t] = nm1;

            float sum0 = 0.f, sum1 = 0.f;
            #pragma unroll
            for (int nt = 0; nt < 8; ++nt) {
                s[nt].x = fexp2(s[nt].x - nm0);
                s[nt].y = fexp2(s[nt].y - nm0);
                s[nt].z = fexp2(s[nt].z - nm1);
                s[nt].w = fexp2(s[nt].w - nm1);
                sum0 += s[nt].x + s[nt].y;
                sum1 += s[nt].z + s[nt].w;
            }
            sum0 += __shfl_xor_sync(FULL, sum0, 1);
            sum0 += __shfl_xor_sync(FULL, sum0, 2);
            sum1 += __shfl_xor_sync(FULL, sum1, 1);
            sum1 += __shfl_xor_sync(FULL, sum1, 2);
            l0[t] = l0[t] * al0 + sum0;
            l1[t] = l1[t] * al1 + sum1;
            #pragma unroll
            for (int nt = 0; nt < 8; ++nt) {
                o[t][nt].x *= al0; o[t][nt].y *= al0;
                o[t][nt].z *= al1; o[t][nt].w *= al1;
            }

            // ---- O += P @ V (P fragments via intra-quad shuffles) ----
            #pragma unroll
            for (int ks = 0; ks < 8; ++ks) {
                const int src  = (lane & ~3) | (qp >> 1);
                const int src2 = src + 2;
                float fx = __shfl_sync(FULL, s[ks].x, src);
                float fy = __shfl_sync(FULL, s[ks].y, src);
                float fz = __shfl_sync(FULL, s[ks].z, src);
                float fw = __shfl_sync(FULL, s[ks].w, src);
                float gx = __shfl_sync(FULL, s[ks].x, src2);
                float gy = __shfl_sync(FULL, s[ks].y, src2);
                float gz = __shfl_sync(FULL, s[ks].z, src2);
                float gw = __shfl_sync(FULL, s[ks].w, src2);
                const bool odd = qp & 1;
                unsigned a0 = f2tf32u(odd ? fy : fx);
                unsigned a1 = f2tf32u(odd ? fw : fz);
                unsigned a2 = f2tf32u(odd ? gy : gx);
                unsigned a3 = f2tf32u(odd ? gw : gz);
                const int keyb = ks * 8 + qp;
                #pragma unroll
                for (int nt = 0; nt < 8; ++nt) {
                    mma8(o[t][nt], a0, a1, a2, a3,
                         fasu(Vs[keyb * 68 + nt * 8 + qr]),
                         fasu(Vs[(keyb + 4) * 68 + nt * 8 + qr]));
                }
            }
        }
        __syncthreads();
    }

    // ---- writeout (tf32-rounded; feeds GEMM2) ----
    #pragma unroll
    for (int t = 0; t < 2; ++t) {
        const float inv0 = 1.f / l0[t], inv1 = 1.f / l1[t];
        const int rg0 = b * TT + q0 + w*32 + t*16 + qr;
        float* ob = out + (size_t)rg0 * CC + h * HD;
        #pragma unroll
        for (int nt = 0; nt < 8; ++nt) {
            int c = nt * 8 + 2 * qp;
            *(float2*)(ob + c) =
                make_float2(f2tf32f(o[t][nt].x * inv0), f2tf32f(o[t][nt].y * inv0));
            *(float2*)(ob + (size_t)8 * CC + c) =
                make_float2(f2tf32f(o[t][nt].z * inv1), f2tf32f(o[t][nt].w * inv1));
        }
    }
}

// ---------------------------------------------------------------------------
extern "C" void kernel_launch(void* const* d_in, const int* in_sizes, int n_in,
                              void* d_out, int out_size)
{
    (void)in_sizes; (void)n_in; (void)out_size;
    const float* x     = (const float*)d_in[0];
    const float* w_qkv = (const float*)d_in[1];
    const float* b_qkv = (const float*)d_in[2];
    const float* w_out = (const float*)d_in[3];
    const float* b_out = (const float*)d_in[4];
    float* out = (float*)d_out;

    float *qkv, *att, *xc, *wqkv, *wout;
    cudaGetSymbolAddress((void**)&qkv,  g_qkv);
    cudaGetSymbolAddress((void**)&att,  g_att);
    cudaGetSymbolAddress((void**)&xc,   g_xc);
    cudaGetSymbolAddress((void**)&wqkv, g_wqkv);
    cudaGetSymbolAddress((void**)&wout, g_wout);

    const int GEMM_SMEM = 3 * 4736 * 4;     // 56832 B
    const int ATTN_SMEM = 4 * 64 * 68 * 4;  // 69632 B
    cudaFuncSetAttribute(gemm_cpa<true>,  cudaFuncAttributeMaxDynamicSharedMemorySize, GEMM_SMEM);
    cudaFuncSetAttribute(gemm_cpa<false>, cudaFuncAttributeMaxDynamicSharedMemorySize, GEMM_SMEM);
    cudaFuncSetAttribute(attn_tf32, cudaFuncAttributeMaxDynamicSharedMemorySize, ATTN_SMEM);

    // 0) prepass: tf32-round x and weights
    cvt_copy<<<(MROWS * CC / 4 + 255) / 256, 256>>>(x, xc, MROWS * CC / 4);
    cvt_copy<<<(CC * 3 * CC / 4 + 255) / 256, 256>>>(w_qkv, wqkv, CC * 3 * CC / 4);
    cvt_copy<<<(CC * CC / 4 + 255) / 256, 256>>>(w_out, wout, CC * CC / 4);

    // 1) qkv = x @ w_qkv + b_qkv   (M=4096, N=3072, K=1024), output tf32-rounded
    {
        dim3 grid(3 * CC / 128, MROWS / 128);
        gemm_cpa<true><<<grid, 256, GEMM_SMEM>>>(xc, wqkv, b_qkv, qkv, MROWS, 3 * CC, CC);
    }
    // 2) fused causal attention -> att [B*T, C] (tf32-rounded)
    {
        dim3 grid(TT / 128, NH, BB);
        attn_tf32<<<grid, 128, ATTN_SMEM>>>(qkv, att);
    }
    // 3) out = att @ w_out + b_out (M=4096, N=1024, K=1024), fp32 output
    {
        dim3 grid(CC / 128, MROWS / 128);
        gemm_cpa<false><<<grid, 256, GEMM_SMEM>>>(att, wout, b_out, out, MROWS, CC, CC);
    }
}

// round 8
// speedup vs baseline: 1.3579x; 1.3579x over previous
#include <cuda_runtime.h>
#include <cuda_fp16.h>
#include <cstdint>

// Problem constants: B=2, T=2048, C=1024, H=16, D=64
#define BB   2
#define TT   2048
#define CC   1024
#define NH   16
#define HD   64
#define MROWS (BB*TT)          // 4096

// Scratch buffers (no cudaMalloc allowed)
__device__ float  g_qkv[(size_t)MROWS * 3 * CC];     // [B*T, 3C] fp32 (GEMM1 out)
__device__ __half g_atth[(size_t)MROWS * CC];        // attention out, half
__device__ __half g_xh[(size_t)MROWS * CC];          // x, half
__device__ __half g_wqkvT[(size_t)3 * CC * CC];      // w_qkv^T [3C][C], half
__device__ __half g_woutT[(size_t)CC * CC];          // w_out^T [C][C], half

// ---------------------------------------------------------------------------
// helpers
// ---------------------------------------------------------------------------
__device__ __forceinline__ unsigned f2tf32u(float x) {
    unsigned r; asm("cvt.rna.tf32.f32 %0, %1;" : "=r"(r) : "f"(x)); return r;
}
__device__ __forceinline__ float f2tf32f(float x) {
    return __uint_as_float(f2tf32u(x));
}
__device__ __forceinline__ unsigned fasu(float x) { return __float_as_uint(x); }

__device__ __forceinline__ uint32_t smem_u32(const void* p) {
    uint32_t a;
    asm("{ .reg .u64 t; cvta.to.shared.u64 t, %1; cvt.u32.u64 %0, t; }" : "=r"(a) : "l"(p));
    return a;
}
__device__ __forceinline__ void cpa16(uint32_t dst, const void* src) {
    asm volatile("cp.async.cg.shared.global [%0], [%1], 16;" :: "r"(dst), "l"(src));
}
#define CPA_COMMIT()  asm volatile("cp.async.commit_group;" ::: "memory")
#define CPA_WAIT(n)   asm volatile("cp.async.wait_group %0;" :: "n"(n) : "memory")

// fp16 mma: D(16x8,f32) += A(16x16,f16) @ B(16x8,f16)
__device__ __forceinline__ void mma16(float4& d,
    unsigned a0, unsigned a1, unsigned a2, unsigned a3,
    unsigned b0, unsigned b1)
{
    asm volatile(
        "mma.sync.aligned.m16n8k16.row.col.f32.f16.f16.f32 "
        "{%0,%1,%2,%3}, {%4,%5,%6,%7}, {%8,%9}, {%0,%1,%2,%3};\n"
        : "+f"(d.x), "+f"(d.y), "+f"(d.z), "+f"(d.w)
        : "r"(a0), "r"(a1), "r"(a2), "r"(a3), "r"(b0), "r"(b1));
}

// tf32 mma (attention)
__device__ __forceinline__ void mma8(float4& d,
    unsigned a0, unsigned a1, unsigned a2, unsigned a3,
    unsigned b0, unsigned b1)
{
    asm volatile(
        "mma.sync.aligned.m16n8k8.row.col.f32.tf32.tf32.f32 "
        "{%0,%1,%2,%3}, {%4,%5,%6,%7}, {%8,%9}, {%0,%1,%2,%3};\n"
        : "+f"(d.x), "+f"(d.y), "+f"(d.z), "+f"(d.w)
        : "r"(a0), "r"(a1), "r"(a2), "r"(a3), "r"(b0), "r"(b1));
}

// ---------------------------------------------------------------------------
// prepass: fp32 -> half elementwise
// ---------------------------------------------------------------------------
__global__ void cvt_h(const float* __restrict__ in, __half* __restrict__ out, int n4)
{
    int i = blockIdx.x * blockDim.x + threadIdx.x;
    if (i < n4) {
        float4 v = ((const float4*)in)[i];
        __half2 h0 = __float22half2_rn(make_float2(v.x, v.y));
        __half2 h1 = __float22half2_rn(make_float2(v.z, v.w));
        ((__half2*)out)[2 * i]     = h0;
        ((__half2*)out)[2 * i + 1] = h1;
    }
}

// prepass: out[c][r] = half(in[r][c]);  in: R x Cn fp32
__global__ void transpose_h(const float* __restrict__ in, __half* __restrict__ out,
                            int R, int Cn)
{
    __shared__ float t[32][33];
    int bx = blockIdx.x * 32, by = blockIdx.y * 32;
    int tx = threadIdx.x, ty = threadIdx.y;
    #pragma unroll
    for (int j = 0; j < 32; j += 8)
        t[ty + j][tx] = in[(size_t)(by + ty + j) * Cn + bx + tx];
    __syncthreads();
    #pragma unroll
    for (int j = 0; j < 32; j += 8)
        out[(size_t)(bx + ty + j) * R + by + tx] = __float2half_rn(t[tx][ty + j]);
}

// ---------------------------------------------------------------------------
// fp16 GEMM: C[M,N] = A[M,K] @ Bt[N,K]^T + bias[N]   (A, Bt half, K-contig)
// 128x128 CTA tile, BK=32, 256 threads (8 warps, 2m x 4n), warp tile 64x32.
// smem (u32 view): per stage A 128x20 + B 128x20 = 5120 u32; 3 stages.
// Fragment u32 loads at bank (20*qr+qp) -> conflict-free.
// ---------------------------------------------------------------------------
__global__ __launch_bounds__(256) void gemm_h(
    const __half* __restrict__ A, const __half* __restrict__ Bt,
    const float* __restrict__ bias, float* __restrict__ C,
    int M, int N, int K)
{
    extern __shared__ uint32_t smu[];
    const int STG = 5120;                 // u32 per stage
    const uint32_t sbase = smem_u32(smu);

    const int tid  = threadIdx.x;
    const int lane = tid & 31, warp = tid >> 5;
    const int wm = warp & 1;              // 64-row half
    const int wn = warp >> 1;             // 32-col quarter
    const int qp = lane & 3, qr = lane >> 2;
    const int brow = blockIdx.y * 128;
    const int bcol = blockIdx.x * 128;

    float4 acc[4][4];
    #pragma unroll
    for (int i = 0; i < 4; ++i)
        #pragma unroll
        for (int j = 0; j < 4; ++j) acc[i][j] = make_float4(0.f, 0.f, 0.f, 0.f);

    const int NCH = K >> 5;               // 32-half K chunks

    // load roles: row = tid>>1 (0..127), half-row part p = tid&1
    const int ar = tid >> 1, p = tid & 1;
    const __half* Ag = A  + (size_t)(brow + ar) * K + p * 16;
    const __half* Bg = Bt + (size_t)(bcol + ar) * K + p * 16;
    const uint32_t dA = (ar * 20 + p * 8) * 4;      // byte offset in stage

    auto load_stage = [&](int kt) {
        uint32_t base = sbase + (kt % 3) * STG * 4;
        cpa16(base + dA,                  Ag + (size_t)kt * 32);
        cpa16(base + dA + 16,             Ag + (size_t)kt * 32 + 8);
        cpa16(base + 2560 * 4 + dA,       Bg + (size_t)kt * 32);
        cpa16(base + 2560 * 4 + dA + 16,  Bg + (size_t)kt * 32 + 8);
        CPA_COMMIT();
    };

    load_stage(0);
    load_stage(1);

    for (int kt = 0; kt < NCH; ++kt) {
        if (kt + 1 < NCH) { CPA_WAIT(1); } else { CPA_WAIT(0); }
        __syncthreads();
        if (kt + 2 < NCH) load_stage(kt + 2);   // safe: past barrier, stage free

        const uint32_t* As = smu + (kt % 3) * STG;
        const uint32_t* Bs = As + 2560;
        #pragma unroll
        for (int ks = 0; ks < 2; ++ks) {
            const int cb = ks * 8 + qp;
            unsigned af[4][4];
            #pragma unroll
            for (int mt = 0; mt < 4; ++mt) {
                int r = wm * 64 + mt * 16 + qr;
                af[mt][0] = As[r * 20 + cb];
                af[mt][1] = As[(r + 8) * 20 + cb];
                af[mt][2] = As[r * 20 + cb + 4];
                af[mt][3] = As[(r + 8) * 20 + cb + 4];
            }
            unsigned bf[4][2];
            #pragma unroll
            for (int nt = 0; nt < 4; ++nt) {
                int c = wn * 32 + nt * 8 + qr;
                bf[nt][0] = Bs[c * 20 + cb];
                bf[nt][1] = Bs[c * 20 + cb + 4];
            }
            #pragma unroll
            for (int mt = 0; mt < 4; ++mt)
                #pragma unroll
                for (int nt = 0; nt < 4; ++nt)
                    mma16(acc[mt][nt], af[mt][0], af[mt][1], af[mt][2], af[mt][3],
                          bf[nt][0], bf[nt][1]);
        }
        __syncthreads();
    }

    // ---- epilogue ----
    #pragma unroll
    for (int mt = 0; mt < 4; ++mt) {
        int r0 = brow + wm * 64 + mt * 16 + qr;
        #pragma unroll
        for (int nt = 0; nt < 4; ++nt) {
            int c = bcol + wn * 32 + nt * 8 + 2 * qp;
            float bx = bias[c], by = bias[c + 1];
            *(float2*)(C + (size_t)r0       * N + c) =
                make_float2(acc[mt][nt].x + bx, acc[mt][nt].y + by);
            *(float2*)(C + (size_t)(r0 + 8) * N + c) =
                make_float2(acc[mt][nt].z + bx, acc[mt][nt].w + by);
        }
    }
}

// ---------------------------------------------------------------------------
// Flash attention, tf32 mma (proven R4 version). Reads fp32 qkv,
// writes HALF att for the fp16 out-projection GEMM.
// CTA: 64 q-rows (4 warps x 16), k-tiles of 64.
// ---------------------------------------------------------------------------
__global__ __launch_bounds__(128) void attn_tf32(
    const float* __restrict__ qkv, __half* __restrict__ out)
{
    __shared__ float Ks[64][68];
    __shared__ float Vs[64][72];

    const int tid  = threadIdx.x;
    const int lane = tid & 31, w = tid >> 5;
    const int h = blockIdx.y, b = blockIdx.z;
    const int q0 = blockIdx.x * 64;
    const int qp = lane & 3;
    const int qr = lane >> 2;
    const unsigned FULL = 0xffffffffu;
    const float scale = 0.125f;

    unsigned qa[8][4];
    {
        const float* Qg = qkv + (size_t)(b*TT + q0 + w*16) * (3*CC) + h*HD;
        #pragma unroll
        for (int ks = 0; ks < 8; ++ks) {
            int c0 = ks * 8 + qp;
            qa[ks][0] = f2tf32u(Qg[(size_t)qr     * (3*CC) + c0    ] * scale);
            qa[ks][1] = f2tf32u(Qg[(size_t)(qr+8) * (3*CC) + c0    ] * scale);
            qa[ks][2] = f2tf32u(Qg[(size_t)qr     * (3*CC) + c0 + 4] * scale);
            qa[ks][3] = f2tf32u(Qg[(size_t)(qr+8) * (3*CC) + c0 + 4] * scale);
        }
    }

    float4 o[8];
    #pragma unroll
    for (int i = 0; i < 8; ++i) o[i] = make_float4(0.f, 0.f, 0.f, 0.f);
    float m0 = -1e30f, m1 = -1e30f, l0 = 0.f, l1 = 0.f;

    const int ndiag = q0 >> 6;
    for (int kt = 0; kt <= ndiag; ++kt) {
        __syncthreads();
        {
            const float* kb = qkv + (size_t)(b*TT + kt*64) * (3*CC) + CC + h*HD;
            const float* vb = kb + CC;
            #pragma unroll
            for (int i = 0; i < 8; ++i) {
                int idx = i * 128 + tid;
                int key = idx >> 4, d4 = (idx & 15) * 4;
                float4 kv = *(const float4*)(kb + (size_t)key * (3*CC) + d4);
                float4 vv = *(const float4*)(vb + (size_t)key * (3*CC) + d4);
                *(float4*)&Ks[key][d4] = make_float4(f2tf32f(kv.x), f2tf32f(kv.y),
                                                     f2tf32f(kv.z), f2tf32f(kv.w));
                *(float4*)&Vs[key][d4] = make_float4(f2tf32f(vv.x), f2tf32f(vv.y),
                                                     f2tf32f(vv.z), f2tf32f(vv.w));
            }
        }
        __syncthreads();

        float4 s[8];
        #pragma unroll
        for (int nt = 0; nt < 8; ++nt) s[nt] = make_float4(0.f, 0.f, 0.f, 0.f);
        #pragma unroll
        for (int nt = 0; nt < 8; ++nt) {
            const int key = nt * 8 + qr;
            #pragma unroll
            for (int ks = 0; ks < 8; ++ks) {
                const int d = ks * 8 + qp;
                unsigned b0 = fasu(Ks[key][d]);
                unsigned b1 = fasu(Ks[key][d + 4]);
                mma8(s[nt], qa[ks][0], qa[ks][1], qa[ks][2], qa[ks][3], b0, b1);
            }
        }

        if (kt == ndiag) {
            const int rg0 = q0 + w * 16 + qr;
            const int rg1 = rg0 + 8;
            #pragma unroll
            for (int nt = 0; nt < 8; ++nt) {
                int cg = kt * 64 + nt * 8 + 2 * qp;
                if (cg     > rg0) s[nt].x = -1e30f;
                if (cg + 1 > rg0) s[nt].y = -1e30f;
                if (cg     > rg1) s[nt].z = -1e30f;
                if (cg + 1 > rg1) s[nt].w = -1e30f;
            }
        }

        float mx0 = -1e30f, mx1 = -1e30f;
        #pragma unroll
        for (int nt = 0; nt < 8; ++nt) {
            mx0 = fmaxf(mx0, fmaxf(s[nt].x, s[nt].y));
            mx1 = fmaxf(mx1, fmaxf(s[nt].z, s[nt].w));
        }
        mx0 = fmaxf(mx0, __shfl_xor_sync(FULL, mx0, 1));
        mx0 = fmaxf(mx0, __shfl_xor_sync(FULL, mx0, 2));
        mx1 = fmaxf(mx1, __shfl_xor_sync(FULL, mx1, 1));
        mx1 = fmaxf(mx1, __shfl_xor_sync(FULL, mx1, 2));

        float nm0 = fmaxf(m0, mx0), nm1 = fmaxf(m1, mx1);
        float al0 = __expf(m0 - nm0), al1 = __expf(m1 - nm1);
        m0 = nm0; m1 = nm1;

        float sum0 = 0.f, sum1 = 0.f;
        #pragma unroll
        for (int nt = 0; nt < 8; ++nt) {
            s[nt].x = __expf(s[nt].x - m0);
            s[nt].y = __expf(s[nt].y - m0);
            s[nt].z = __expf(s[nt].z - m1);
            s[nt].w = __expf(s[nt].w - m1);
            sum0 += s[nt].x + s[nt].y;
            sum1 += s[nt].z + s[nt].w;
        }
        sum0 += __shfl_xor_sync(FULL, sum0, 1);
        sum0 += __shfl_xor_sync(FULL, sum0, 2);
        sum1 += __shfl_xor_sync(FULL, sum1, 1);
        sum1 += __shfl_xor_sync(FULL, sum1, 2);
        l0 = l0 * al0 + sum0;
        l1 = l1 * al1 + sum1;
        #pragma unroll
        for (int nt = 0; nt < 8; ++nt) {
            o[nt].x *= al0; o[nt].y *= al0; o[nt].z *= al1; o[nt].w *= al1;
        }

        #pragma unroll
        for (int ks = 0; ks < 8; ++ks) {
            const int src  = (lane & ~3) | (qp >> 1);
            const int src2 = src + 2;
            float fx = __shfl_sync(FULL, s[ks].x, src);
            float fy = __shfl_sync(FULL, s[ks].y, src);
            float fz = __shfl_sync(FULL, s[ks].z, src);
            float fw = __shfl_sync(FULL, s[ks].w, src);
            float gx = __shfl_sync(FULL, s[ks].x, src2);
            float gy = __shfl_sync(FULL, s[ks].y, src2);
            float gz = __shfl_sync(FULL, s[ks].z, src2);
            float gw = __shfl_sync(FULL, s[ks].w, src2);
            const bool odd = qp & 1;
            unsigned a0 = f2tf32u(odd ? fy : fx);
            unsigned a1 = f2tf32u(odd ? fw : fz);
            unsigned a2 = f2tf32u(odd ? gy : gx);
            unsigned a3 = f2tf32u(odd ? gw : gz);
            const int keyb = ks * 8 + qp;
            #pragma unroll
            for (int nt = 0; nt < 8; ++nt) {
                unsigned b0 = fasu(Vs[keyb    ][nt * 8 + qr]);
                unsigned b1 = fasu(Vs[keyb + 4][nt * 8 + qr]);
                mma8(o[nt], a0, a1, a2, a3, b0, b1);
            }
        }
    }

    // ---- writeout to HALF [B*T, C] ----
    const float inv0 = 1.f / l0, inv1 = 1.f / l1;
    const int rg0 = b * TT + q0 + w * 16 + qr;
    __half* ob = out + (size_t)rg0 * CC + h * HD;
    #pragma unroll
    for (int nt = 0; nt < 8; ++nt) {
        int c = nt * 8 + 2 * qp;
        *(__half2*)(ob + c) =
            __float22half2_rn(make_float2(o[nt].x * inv0, o[nt].y * inv0));
        *(__half2*)(ob + (size_t)8 * CC + c) =
            __float22half2_rn(make_float2(o[nt].z * inv1, o[nt].w * inv1));
    }
}

// ---------------------------------------------------------------------------
extern "C" void kernel_launch(void* const* d_in, const int* in_sizes, int n_in,
                              void* d_out, int out_size)
{
    (void)in_sizes; (void)n_in; (void)out_size;
    const float* x     = (const float*)d_in[0];
    const float* w_qkv = (const float*)d_in[1];
    const float* b_qkv = (const float*)d_in[2];
    const float* w_out = (const float*)d_in[3];
    const float* b_out = (const float*)d_in[4];
    float* out = (float*)d_out;

    float  *qkv;
    __half *atth, *xh, *wqkvT, *woutT;
    cudaGetSymbolAddress((void**)&qkv,   g_qkv);
    cudaGetSymbolAddress((void**)&atth,  g_atth);
    cudaGetSymbolAddress((void**)&xh,    g_xh);
    cudaGetSymbolAddress((void**)&wqkvT, g_wqkvT);
    cudaGetSymbolAddress((void**)&woutT, g_woutT);

    const int GEMM_SMEM = 3 * 5120 * 4;   // 61440 B
    cudaFuncSetAttribute(gemm_h, cudaFuncAttributeMaxDynamicSharedMemorySize, GEMM_SMEM);

    // 0) prepass: x -> half; weights -> transposed half [N][K]
    cvt_h<<<(MROWS * CC / 4 + 255) / 256, 256>>>(x, xh, MROWS * CC / 4);
    {
        dim3 blk(32, 8);
        transpose_h<<<dim3(3 * CC / 32, CC / 32), blk>>>(w_qkv, wqkvT, CC, 3 * CC);
        transpose_h<<<dim3(CC / 32, CC / 32), blk>>>(w_out, woutT, CC, CC);
    }

    // 1) qkv = x @ w_qkv + b_qkv   (M=4096, N=3072, K=1024) -> fp32
    {
        dim3 grid(3 * CC / 128, MROWS / 128);
        gemm_h<<<grid, 256, GEMM_SMEM>>>(xh, wqkvT, b_qkv, qkv, MROWS, 3 * CC, CC);
    }
    // 2) fused causal attention -> atth (half) [B*T, C]
    {
        dim3 grid(TT / 64, NH, BB);
        attn_tf32<<<grid, 128>>>(qkv, atth);
    }
    // 3) out = att @ w_out + b_out (M=4096, N=1024, K=1024) -> fp32
    {
        dim3 grid(CC / 128, MROWS / 128);
        gemm_h<<<grid, 256, GEMM_SMEM>>>(atth, woutT, b_out, out, MROWS, CC, CC);
    }
}